// round 1
// baseline (speedup 1.0000x reference)
#include <cuda_runtime.h>
#include <math.h>

#define NROWS 8192
#define DHID  512
#define BM 128
#define BN 128
#define BK 16

// Scratch (allocation-free rule: __device__ globals)
__device__ float g_q[(size_t)NROWS * DHID];
__device__ float g_k[(size_t)NROWS * DHID];
__device__ float g_v[(size_t)NROWS * DHID];
__device__ float g_E[(size_t)NROWS * NROWS];
__device__ float g_rowsum[NROWS];

__global__ void zero_rowsum_k() {
    g_rowsum[blockIdx.x * blockDim.x + threadIdx.x] = 0.0f;
}

// C[M,N] = epilogue( A[M,K] * B )
//   BTRANS=1: B is [N,K] row-major (C = A * B^T)   -- used for Q*K^T
//   BTRANS=0: B is [K,N] row-major                  -- used for x*W and E*v
// EPI 0: C = |acc|
// EPI 1: C = exp(acc*scale), rsum[row] += row-partials (atomic)
// EPI 2: C = acc / rsum[row]
template<int EPI, int BTRANS>
__global__ __launch_bounds__(256, 2)
void gemm_k(const float* __restrict__ A, const float* __restrict__ B,
            float* __restrict__ C, float* __restrict__ rsum,
            int M, int N, int K, float scale)
{
    __shared__ float As[2][BK][BM];
    __shared__ float Bs[2][BK][BN];
    __shared__ float red[BM][16];

    const int tid = threadIdx.x;
    const int tx = tid & 15;
    const int ty = tid >> 4;
    const int m0 = blockIdx.y * BM;
    const int n0 = blockIdx.x * BN;

    // A tile load mapping: 128 rows x 16 k -> 512 float4, 2 per thread
    const int a_r = tid >> 2;          // 0..63
    const int a_c = (tid & 3) << 2;    // 0,4,8,12
    const float* Ap = A + (size_t)(m0 + a_r) * K + a_c;

    const float* Bp;
    int b_r = 0, b_c = 0;
    if (BTRANS) {
        Bp = B + (size_t)(n0 + a_r) * K + a_c;
    } else {
        b_r = tid >> 5;                // 0..7
        b_c = (tid & 31) << 2;         // 0..124
        Bp = B + (size_t)b_r * N + n0 + b_c;
    }

    float acc[8][8];
    #pragma unroll
    for (int i = 0; i < 8; i++)
        #pragma unroll
        for (int j = 0; j < 8; j++) acc[i][j] = 0.0f;

    const int nkt = K / BK;
    float4 pa0, pa1, pb0, pb1;

    // ---- prologue: fetch + stage tile 0 ----
    pa0 = *(const float4*)(Ap);
    pa1 = *(const float4*)(Ap + (size_t)64 * K);
    if (BTRANS) {
        pb0 = *(const float4*)(Bp);
        pb1 = *(const float4*)(Bp + (size_t)64 * K);
    } else {
        pb0 = *(const float4*)(Bp);
        pb1 = *(const float4*)(Bp + (size_t)8 * N);
    }
    {
        As[0][a_c+0][a_r]    = pa0.x; As[0][a_c+1][a_r]    = pa0.y;
        As[0][a_c+2][a_r]    = pa0.z; As[0][a_c+3][a_r]    = pa0.w;
        As[0][a_c+0][a_r+64] = pa1.x; As[0][a_c+1][a_r+64] = pa1.y;
        As[0][a_c+2][a_r+64] = pa1.z; As[0][a_c+3][a_r+64] = pa1.w;
        if (BTRANS) {
            Bs[0][a_c+0][a_r]    = pb0.x; Bs[0][a_c+1][a_r]    = pb0.y;
            Bs[0][a_c+2][a_r]    = pb0.z; Bs[0][a_c+3][a_r]    = pb0.w;
            Bs[0][a_c+0][a_r+64] = pb1.x; Bs[0][a_c+1][a_r+64] = pb1.y;
            Bs[0][a_c+2][a_r+64] = pb1.z; Bs[0][a_c+3][a_r+64] = pb1.w;
        } else {
            *(float4*)&Bs[0][b_r][b_c]   = pb0;
            *(float4*)&Bs[0][b_r+8][b_c] = pb1;
        }
    }
    __syncthreads();

    int buf = 0;
    for (int kt = 1; kt <= nkt; ++kt) {
        if (kt < nkt) {
            const float* Ak = Ap + (size_t)kt * BK;
            pa0 = *(const float4*)(Ak);
            pa1 = *(const float4*)(Ak + (size_t)64 * K);
            if (BTRANS) {
                const float* Bk = Bp + (size_t)kt * BK;
                pb0 = *(const float4*)(Bk);
                pb1 = *(const float4*)(Bk + (size_t)64 * K);
            } else {
                const float* Bk = Bp + (size_t)(kt * BK) * N;
                pb0 = *(const float4*)(Bk);
                pb1 = *(const float4*)(Bk + (size_t)8 * N);
            }
        }
        #pragma unroll
        for (int k = 0; k < BK; ++k) {
            float4 a0 = *(const float4*)&As[buf][k][ty * 8];
            float4 a1 = *(const float4*)&As[buf][k][ty * 8 + 4];
            float4 b0 = *(const float4*)&Bs[buf][k][tx * 8];
            float4 b1 = *(const float4*)&Bs[buf][k][tx * 8 + 4];
            float av[8] = {a0.x, a0.y, a0.z, a0.w, a1.x, a1.y, a1.z, a1.w};
            float bv[8] = {b0.x, b0.y, b0.z, b0.w, b1.x, b1.y, b1.z, b1.w};
            #pragma unroll
            for (int i = 0; i < 8; i++)
                #pragma unroll
                for (int j = 0; j < 8; j++)
                    acc[i][j] += av[i] * bv[j];
        }
        if (kt < nkt) {
            const int nb = buf ^ 1;
            As[nb][a_c+0][a_r]    = pa0.x; As[nb][a_c+1][a_r]    = pa0.y;
            As[nb][a_c+2][a_r]    = pa0.z; As[nb][a_c+3][a_r]    = pa0.w;
            As[nb][a_c+0][a_r+64] = pa1.x; As[nb][a_c+1][a_r+64] = pa1.y;
            As[nb][a_c+2][a_r+64] = pa1.z; As[nb][a_c+3][a_r+64] = pa1.w;
            if (BTRANS) {
                Bs[nb][a_c+0][a_r]    = pb0.x; Bs[nb][a_c+1][a_r]    = pb0.y;
                Bs[nb][a_c+2][a_r]    = pb0.z; Bs[nb][a_c+3][a_r]    = pb0.w;
                Bs[nb][a_c+0][a_r+64] = pb1.x; Bs[nb][a_c+1][a_r+64] = pb1.y;
                Bs[nb][a_c+2][a_r+64] = pb1.z; Bs[nb][a_c+3][a_r+64] = pb1.w;
            } else {
                *(float4*)&Bs[nb][b_r][b_c]   = pb0;
                *(float4*)&Bs[nb][b_r+8][b_c] = pb1;
            }
        }
        __syncthreads();
        buf ^= 1;
    }

    const int row0 = m0 + ty * 8;
    const int col0 = n0 + tx * 8;

    if (EPI == 0) {
        #pragma unroll
        for (int i = 0; i < 8; i++) {
            float4 o0 = make_float4(fabsf(acc[i][0]), fabsf(acc[i][1]),
                                    fabsf(acc[i][2]), fabsf(acc[i][3]));
            float4 o1 = make_float4(fabsf(acc[i][4]), fabsf(acc[i][5]),
                                    fabsf(acc[i][6]), fabsf(acc[i][7]));
            *(float4*)&C[(size_t)(row0 + i) * N + col0]     = o0;
            *(float4*)&C[(size_t)(row0 + i) * N + col0 + 4] = o1;
        }
    } else if (EPI == 1) {
        float rp[8];
        #pragma unroll
        for (int i = 0; i < 8; i++) {
            rp[i] = 0.0f;
            #pragma unroll
            for (int j = 0; j < 8; j++) {
                float e = __expf(acc[i][j] * scale);
                acc[i][j] = e;
                rp[i] += e;
            }
            float4 o0 = make_float4(acc[i][0], acc[i][1], acc[i][2], acc[i][3]);
            float4 o1 = make_float4(acc[i][4], acc[i][5], acc[i][6], acc[i][7]);
            *(float4*)&C[(size_t)(row0 + i) * N + col0]     = o0;
            *(float4*)&C[(size_t)(row0 + i) * N + col0 + 4] = o1;
        }
        #pragma unroll
        for (int i = 0; i < 8; i++) red[ty * 8 + i][tx] = rp[i];
        __syncthreads();
        if (tid < BM) {
            float s = 0.0f;
            #pragma unroll
            for (int j = 0; j < 16; j++) s += red[tid][j];
            atomicAdd(&rsum[m0 + tid], s);
        }
    } else {
        #pragma unroll
        for (int i = 0; i < 8; i++) {
            float rs = rsum[row0 + i];
            float4 o0 = make_float4(acc[i][0] / rs, acc[i][1] / rs,
                                    acc[i][2] / rs, acc[i][3] / rs);
            float4 o1 = make_float4(acc[i][4] / rs, acc[i][5] / rs,
                                    acc[i][6] / rs, acc[i][7] / rs);
            *(float4*)&C[(size_t)(row0 + i) * N + col0]     = o0;
            *(float4*)&C[(size_t)(row0 + i) * N + col0 + 4] = o1;
        }
    }
}

extern "C" void kernel_launch(void* const* d_in, const int* in_sizes, int n_in,
                              void* d_out, int out_size)
{
    (void)in_sizes; (void)n_in; (void)out_size;
    const float* x  = (const float*)d_in[0];
    const float* Wq = (const float*)d_in[1];
    const float* Wk = (const float*)d_in[2];
    const float* Wv = (const float*)d_in[3];
    float* out = (float*)d_out;

    float *q, *k, *v, *E, *rs;
    cudaGetSymbolAddress((void**)&q,  g_q);
    cudaGetSymbolAddress((void**)&k,  g_k);
    cudaGetSymbolAddress((void**)&v,  g_v);
    cudaGetSymbolAddress((void**)&E,  g_E);
    cudaGetSymbolAddress((void**)&rs, g_rowsum);

    const float inv_sqrt_d = 0.04419417382415922f;  // 1/sqrt(512)
    dim3 blk(256);

    // q, k, v = |x @ W|
    gemm_k<0,0><<<dim3(DHID/BN, NROWS/BM), blk>>>(x, Wq, q, nullptr, NROWS, DHID, DHID, 0.f);
    gemm_k<0,0><<<dim3(DHID/BN, NROWS/BM), blk>>>(x, Wk, k, nullptr, NROWS, DHID, DHID, 0.f);
    gemm_k<0,0><<<dim3(DHID/BN, NROWS/BM), blk>>>(x, Wv, v, nullptr, NROWS, DHID, DHID, 0.f);

    // rowsum accumulator must be zeroed every replay (graph-safe kernel, not memset)
    zero_rowsum_k<<<NROWS/256, 256>>>();

    // E = exp((q @ k^T)/sqrt(d)); rowsum via atomics.
    // Global-max subtraction is dropped: (A/norm) is invariant to the exp(-max/s)
    // factor up to eps/norm ~ 7e-11 << 1e-3, and exp(dot/s) <= ~e^19 fits fp32.
    gemm_k<1,1><<<dim3(NROWS/BN, NROWS/BM), blk>>>(q, k, E, rs, NROWS, NROWS, DHID, inv_sqrt_d);

    // out = (E @ v) / rowsum
    gemm_k<2,0><<<dim3(DHID/BN, NROWS/BM), blk>>>(E, v, out, rs, NROWS, DHID, NROWS, 0.f);
}

// round 3
// speedup vs baseline: 2.9000x; 2.9000x over previous
#include <cuda_runtime.h>
#include <cuda_bf16.h>
#include <stdint.h>
#include <math.h>

#define NR 8192
#define DD 512

// ---------------- scratch (__device__ globals; no allocs allowed) ----------------
__device__ __align__(128) __nv_bfloat16 g_xhi[(size_t)NR * DD];
__device__ __align__(128) __nv_bfloat16 g_xlo[(size_t)NR * DD];
__device__ __align__(128) __nv_bfloat16 g_wth[3][(size_t)DD * DD];   // W^T hi
__device__ __align__(128) __nv_bfloat16 g_wtl[3][(size_t)DD * DD];   // W^T lo
__device__ __align__(128) __nv_bfloat16 g_qhi[(size_t)NR * DD];
__device__ __align__(128) __nv_bfloat16 g_qlo[(size_t)NR * DD];
__device__ __align__(128) __nv_bfloat16 g_khi[(size_t)NR * DD];
__device__ __align__(128) __nv_bfloat16 g_klo[(size_t)NR * DD];
__device__ __align__(128) __nv_bfloat16 g_vb [(size_t)NR * DD];
__device__ __align__(128) __nv_bfloat16 g_vt [(size_t)DD * NR];      // v^T
__device__ __align__(128) __nv_bfloat16 g_E  [(size_t)NR * NR];      // 128 MB
__device__ float g_rowsum[NR];

// ---------------- helpers (arch-generic PTX only: ldmatrix + mma.sync) ----------------
__device__ __forceinline__ uint32_t smem_u32(const void* p) {
    uint32_t a;
    asm("{ .reg .u64 t; cvta.to.shared.u64 t, %1; cvt.u32.u64 %0, t; }" : "=r"(a) : "l"(p));
    return a;
}
__device__ __forceinline__ void ldsm4(uint32_t r[4], uint32_t a) {
    asm volatile("ldmatrix.sync.aligned.m8n8.x4.shared.b16 {%0,%1,%2,%3}, [%4];"
                 : "=r"(r[0]), "=r"(r[1]), "=r"(r[2]), "=r"(r[3]) : "r"(a));
}
__device__ __forceinline__ void mma16816(float d[4], const uint32_t a[4], const uint32_t b[2]) {
    asm volatile("mma.sync.aligned.m16n8k16.row.col.f32.bf16.bf16.f32 "
                 "{%0,%1,%2,%3}, {%4,%5,%6,%7}, {%8,%9}, {%0,%1,%2,%3};"
                 : "+f"(d[0]), "+f"(d[1]), "+f"(d[2]), "+f"(d[3])
                 : "r"(a[0]), "r"(a[1]), "r"(a[2]), "r"(a[3]), "r"(b[0]), "r"(b[1]));
}
__device__ __forceinline__ float exp2_poly(float t) {
    // 2^t for t in [0, ~28]; dot >= 0 always. deg-6 minimax-ish on f in [-0.5, 0.5]
    float fi = rintf(t);
    float f = t - fi;
    float p = 0.00015403530393381606f;
    p = fmaf(p, f, 0.0013333558146428443f);
    p = fmaf(p, f, 0.009618129107628477f);
    p = fmaf(p, f, 0.05550410866482158f);
    p = fmaf(p, f, 0.2402265069591007f);
    p = fmaf(p, f, 0.6931471805599453f);
    p = fmaf(p, f, 1.0f);
    return __int_as_float(((int)fi + 127) << 23) * p;
}

// ---------------- small prep kernels ----------------
__global__ void zero_rowsum_k() { g_rowsum[blockIdx.x * blockDim.x + threadIdx.x] = 0.0f; }

__global__ void split_x_k(const float4* __restrict__ x) {
    size_t i = (size_t)blockIdx.x * 256 + threadIdx.x;
    float4 v = x[i];
    __nv_bfloat16 hx = __float2bfloat16(v.x), hy = __float2bfloat16(v.y);
    __nv_bfloat16 hz = __float2bfloat16(v.z), hw = __float2bfloat16(v.w);
    __nv_bfloat162* H = (__nv_bfloat162*)g_xhi;
    __nv_bfloat162* L = (__nv_bfloat162*)g_xlo;
    H[2 * i]     = __halves2bfloat162(hx, hy);
    H[2 * i + 1] = __halves2bfloat162(hz, hw);
    L[2 * i]     = __halves2bfloat162(__float2bfloat16(v.x - __bfloat162float(hx)),
                                      __float2bfloat16(v.y - __bfloat162float(hy)));
    L[2 * i + 1] = __halves2bfloat162(__float2bfloat16(v.z - __bfloat162float(hz)),
                                      __float2bfloat16(v.w - __bfloat162float(hw)));
}

__global__ void trans_split_w_k(const float* __restrict__ W,
                                __nv_bfloat16* __restrict__ Th,
                                __nv_bfloat16* __restrict__ Tl) {
    __shared__ float t[32][33];
    int tx = threadIdx.x, ty = threadIdx.y;
    int xi = blockIdx.x * 32 + tx, yi = blockIdx.y * 32 + ty;
    #pragma unroll
    for (int i = 0; i < 32; i += 8) t[ty + i][tx] = W[(size_t)(yi + i) * DD + xi];
    __syncthreads();
    int xo = blockIdx.y * 32 + tx, yo = blockIdx.x * 32 + ty;
    #pragma unroll
    for (int i = 0; i < 32; i += 8) {
        float v = t[tx][ty + i];
        __nv_bfloat16 h = __float2bfloat16(v);
        Th[(size_t)(yo + i) * DD + xo] = h;
        Tl[(size_t)(yo + i) * DD + xo] = __float2bfloat16(v - __bfloat162float(h));
    }
}

__global__ void trans_v_k() {
    __shared__ __nv_bfloat16 t[32][33];
    int tx = threadIdx.x, ty = threadIdx.y;
    int xi = blockIdx.x * 32 + tx, yi = blockIdx.y * 32 + ty;   // xi over DD, yi over NR
    #pragma unroll
    for (int i = 0; i < 32; i += 8) t[ty + i][tx] = g_vb[(size_t)(yi + i) * DD + xi];
    __syncthreads();
    int xo = blockIdx.y * 32 + tx, yo = blockIdx.x * 32 + ty;   // xo over NR, yo over DD
    #pragma unroll
    for (int i = 0; i < 32; i += 8) g_vt[(size_t)(yo + i) * NR + xo] = t[tx][ty + i];
}

// ============ mma.sync GEMM: D[M,Ncols] = A[M,K] x B[Ncols,K]^T, bf16, fp32 accum ========
// NOP=2: acc = Ahi*Bhi + Ahi*Blo + Alo*Bhi   NOP=1: acc = A*B
// EPI 0: abs -> split (Chi, Clo)   EPI 1: abs -> bf16 (Chi)
// EPI 2: exp2(acc*scale) -> bf16 Chi + rowsum atomics   EPI 3: acc/rowsum -> f32 Cf
//
// Block tile 128x128, BK=32, 8 warps (2m x 4n), warp tile 64x32 (4x4 m16n8k16).
// smem tiles: 128 rows x 32 cols bf16 (64 B rows), swizzle: 16B-unit' = unit ^ ((row>>1)&3)
// -> conflict-free ldmatrix (banks (row&1)*4 + unit' all distinct across 8 lanes/phase).
template<int NOP, int EPI>
__global__ __launch_bounds__(256, 1)
void mma_gemm(const __nv_bfloat16* __restrict__ Ahi, const __nv_bfloat16* __restrict__ Alo,
              const __nv_bfloat16* __restrict__ Bhi, const __nv_bfloat16* __restrict__ Blo,
              int Ncols, int K,
              __nv_bfloat16* __restrict__ Chi, __nv_bfloat16* __restrict__ Clo,
              float* __restrict__ Cf, float* __restrict__ rsum, float scale)
{
    constexpr int NT = 2 * NOP;             // tiles per buffer
    extern __shared__ char dyn[];
    __shared__ float red[128][4];

    const int tid = threadIdx.x;
    const int lane = tid & 31, wid = tid >> 5;
    const int wm = wid & 1, wn = wid >> 1;
    const int m0 = blockIdx.y * 128, n0 = blockIdx.x * 128;
    const uint32_t sbase = smem_u32(dyn);

    const __nv_bfloat16* gsrc[NT];
    int rb[NT];
    if (NOP == 2) {
        gsrc[0] = Ahi; rb[0] = m0;
        gsrc[1] = Alo; rb[1] = m0;
        gsrc[2] = Bhi; rb[2] = n0;
        gsrc[3] = Blo; rb[3] = n0;
    } else {
        gsrc[0] = Ahi; rb[0] = m0;
        gsrc[1] = Bhi; rb[1] = n0;
    }

    // global->smem store mapping: thread covers 16B units g = tid and tid+256 per tile
    const int su = tid & 3;                  // unit 0..3
    const int sr0 = tid >> 2, sr1 = sr0 + 64;
    const uint32_t soff0 = sr0 * 64 + ((su ^ ((sr0 >> 1) & 3)) << 4);
    const uint32_t soff1 = sr1 * 64 + ((su ^ ((sr1 >> 1) & 3)) << 4);

    // ldmatrix per-lane byte offsets (within a tile)
    uint32_t offA[4][2], offB[2][2];
    {
        const int ra = lane & 15, ua = lane >> 4;
        #pragma unroll
        for (int mi = 0; mi < 4; mi++)
            #pragma unroll
            for (int ks = 0; ks < 2; ks++) {
                int r = wm * 64 + mi * 16 + ra;
                int u = ks * 2 + ua;
                offA[mi][ks] = r * 64 + ((u ^ ((r >> 1) & 3)) << 4);
            }
        const int rbv = ((lane >> 4) << 3) + (lane & 7), ub = (lane >> 3) & 1;
        #pragma unroll
        for (int np = 0; np < 2; np++)
            #pragma unroll
            for (int ks = 0; ks < 2; ks++) {
                int r = wn * 32 + np * 16 + rbv;
                int u = ks * 2 + ub;
                offB[np][ks] = r * 64 + ((u ^ ((r >> 1) & 3)) << 4);
            }
    }

    float acc[4][4][4];
    #pragma unroll
    for (int a = 0; a < 4; a++)
        #pragma unroll
        for (int b = 0; b < 4; b++)
            #pragma unroll
            for (int c = 0; c < 4; c++) acc[a][b][c] = 0.0f;

    const int nkt = K >> 5;

    float4 st[2 * NT];
    #pragma unroll
    for (int t = 0; t < NT; t++) {
        st[2 * t]     = *(const float4*)(gsrc[t] + (size_t)(rb[t] + sr0) * K + su * 8);
        st[2 * t + 1] = *(const float4*)(gsrc[t] + (size_t)(rb[t] + sr1) * K + su * 8);
    }
    #pragma unroll
    for (int t = 0; t < NT; t++) {
        *(float4*)(dyn + t * 8192 + soff0) = st[2 * t];
        *(float4*)(dyn + t * 8192 + soff1) = st[2 * t + 1];
    }
    __syncthreads();

    for (int kt = 0; kt < nkt; kt++) {
        if (kt + 1 < nkt) {
            const int kc = (kt + 1) * 32 + su * 8;
            #pragma unroll
            for (int t = 0; t < NT; t++) {
                st[2 * t]     = *(const float4*)(gsrc[t] + (size_t)(rb[t] + sr0) * K + kc);
                st[2 * t + 1] = *(const float4*)(gsrc[t] + (size_t)(rb[t] + sr1) * K + kc);
            }
        }
        const uint32_t bb = sbase + (uint32_t)((kt & 1) * (NT * 8192));
        #pragma unroll
        for (int ks = 0; ks < 2; ks++) {
            uint32_t ah[4][4];
            #pragma unroll
            for (int mi = 0; mi < 4; mi++) ldsm4(ah[mi], bb + offA[mi][ks]);
            uint32_t bh[2][4];
            constexpr uint32_t TBH = (NOP == 2) ? 2u * 8192u : 1u * 8192u;
            #pragma unroll
            for (int np = 0; np < 2; np++) ldsm4(bh[np], bb + TBH + offB[np][ks]);
            #pragma unroll
            for (int mi = 0; mi < 4; mi++)
                #pragma unroll
                for (int ni = 0; ni < 4; ni++)
                    mma16816(acc[mi][ni], ah[mi], &bh[ni >> 1][(ni & 1) * 2]);
            if (NOP == 2) {
                uint32_t bl[2][4];
                #pragma unroll
                for (int np = 0; np < 2; np++) ldsm4(bl[np], bb + 3u * 8192u + offB[np][ks]);
                #pragma unroll
                for (int mi = 0; mi < 4; mi++)
                    #pragma unroll
                    for (int ni = 0; ni < 4; ni++)
                        mma16816(acc[mi][ni], ah[mi], &bl[ni >> 1][(ni & 1) * 2]);
                uint32_t al[4][4];
                #pragma unroll
                for (int mi = 0; mi < 4; mi++) ldsm4(al[mi], bb + 1u * 8192u + offA[mi][ks]);
                #pragma unroll
                for (int mi = 0; mi < 4; mi++)
                    #pragma unroll
                    for (int ni = 0; ni < 4; ni++)
                        mma16816(acc[mi][ni], al[mi], &bh[ni >> 1][(ni & 1) * 2]);
            }
        }
        if (kt + 1 < nkt) {
            char* db = dyn + ((kt + 1) & 1) * (NT * 8192);
            #pragma unroll
            for (int t = 0; t < NT; t++) {
                *(float4*)(db + t * 8192 + soff0) = st[2 * t];
                *(float4*)(db + t * 8192 + soff1) = st[2 * t + 1];
            }
        }
        __syncthreads();
    }

    // -------- epilogue --------
    // c-frag: regs {0,1}: row lr, cols lc,lc+1; regs {2,3}: row lr+8
    const int lr = lane >> 2;
    const int lc = (lane & 3) << 1;

    #pragma unroll
    for (int mi = 0; mi < 4; mi++) {
        #pragma unroll
        for (int h = 0; h < 2; h++) {
            const int lrow = wm * 64 + mi * 16 + h * 8 + lr;
            const int grow = m0 + lrow;
            float part = 0.0f;
            float invr = 0.0f;
            if (EPI == 3) invr = 1.0f / rsum[grow];
            #pragma unroll
            for (int ni = 0; ni < 4; ni++) {
                float v0 = acc[mi][ni][h * 2 + 0];
                float v1 = acc[mi][ni][h * 2 + 1];
                const int gcol = n0 + wn * 32 + ni * 8 + lc;
                const size_t o = (size_t)grow * Ncols + gcol;
                if (EPI == 0) {
                    float y0 = fabsf(v0), y1 = fabsf(v1);
                    __nv_bfloat16 h0 = __float2bfloat16(y0), h1 = __float2bfloat16(y1);
                    __nv_bfloat16 l0 = __float2bfloat16(y0 - __bfloat162float(h0));
                    __nv_bfloat16 l1 = __float2bfloat16(y1 - __bfloat162float(h1));
                    *(__nv_bfloat162*)(Chi + o) = __halves2bfloat162(h0, h1);
                    *(__nv_bfloat162*)(Clo + o) = __halves2bfloat162(l0, l1);
                } else if (EPI == 1) {
                    *(__nv_bfloat162*)(Chi + o) =
                        __halves2bfloat162(__float2bfloat16(fabsf(v0)),
                                           __float2bfloat16(fabsf(v1)));
                } else if (EPI == 2) {
                    float e0 = exp2_poly(v0 * scale);
                    float e1 = exp2_poly(v1 * scale);
                    part += e0 + e1;
                    *(__nv_bfloat162*)(Chi + o) =
                        __halves2bfloat162(__float2bfloat16(e0), __float2bfloat16(e1));
                } else {
                    *(float2*)(Cf + o) = make_float2(v0 * invr, v1 * invr);
                }
            }
            if (EPI == 2) {
                part += __shfl_xor_sync(0xffffffffu, part, 1);
                part += __shfl_xor_sync(0xffffffffu, part, 2);
                if ((lane & 3) == 0) red[lrow][wn] = part;
            }
        }
    }
    if (EPI == 2) {
        __syncthreads();
        if (tid < 128)
            atomicAdd(&rsum[m0 + tid],
                      red[tid][0] + red[tid][1] + red[tid][2] + red[tid][3]);
    }
}

// ---------------- launch ----------------
extern "C" void kernel_launch(void* const* d_in, const int* in_sizes, int n_in,
                              void* d_out, int out_size)
{
    (void)in_sizes; (void)n_in; (void)out_size;
    const float* x  = (const float*)d_in[0];
    const float* W[3] = {(const float*)d_in[1], (const float*)d_in[2], (const float*)d_in[3]};
    float* out = (float*)d_out;

    __nv_bfloat16 *xhi, *xlo, *wth0, *wtl0, *qhi, *qlo, *khi, *klo, *vb, *vt, *E;
    float* rs;
    cudaGetSymbolAddress((void**)&xhi, g_xhi);
    cudaGetSymbolAddress((void**)&xlo, g_xlo);
    cudaGetSymbolAddress((void**)&wth0, g_wth);
    cudaGetSymbolAddress((void**)&wtl0, g_wtl);
    cudaGetSymbolAddress((void**)&qhi, g_qhi);
    cudaGetSymbolAddress((void**)&qlo, g_qlo);
    cudaGetSymbolAddress((void**)&khi, g_khi);
    cudaGetSymbolAddress((void**)&klo, g_klo);
    cudaGetSymbolAddress((void**)&vb,  g_vb);
    cudaGetSymbolAddress((void**)&vt,  g_vt);
    cudaGetSymbolAddress((void**)&E,   g_E);
    cudaGetSymbolAddress((void**)&rs,  g_rowsum);

    const int SM2 = 4 * 8192 * 2;   // 64 KB (split kernels)
    const int SM1 = 2 * 8192 * 2;   // 32 KB (single)
    cudaFuncSetAttribute(mma_gemm<2, 0>, cudaFuncAttributeMaxDynamicSharedMemorySize, SM2);
    cudaFuncSetAttribute(mma_gemm<2, 1>, cudaFuncAttributeMaxDynamicSharedMemorySize, SM2);
    cudaFuncSetAttribute(mma_gemm<2, 2>, cudaFuncAttributeMaxDynamicSharedMemorySize, SM2);
    cudaFuncSetAttribute(mma_gemm<1, 3>, cudaFuncAttributeMaxDynamicSharedMemorySize, SM1);

    const float SC2 = 0.06375869843f;       // log2(e)/sqrt(512)

    split_x_k<<<(NR * DD / 4) / 256, 256>>>((const float4*)x);
    for (int i = 0; i < 3; i++)
        trans_split_w_k<<<dim3(16, 16), dim3(32, 8)>>>(W[i], wth0 + (size_t)i * DD * DD,
                                                       wtl0 + (size_t)i * DD * DD);
    zero_rowsum_k<<<NR / 256, 256>>>();

    dim3 blk(256);
    dim3 gQKV(DD / 128, NR / 128);

    // q,k: |x W| split; v: |x W| bf16
    mma_gemm<2, 0><<<gQKV, blk, SM2>>>(xhi, xlo, wth0, wtl0, DD, DD,
                                       qhi, qlo, nullptr, nullptr, 0.f);
    mma_gemm<2, 0><<<gQKV, blk, SM2>>>(xhi, xlo, wth0 + (size_t)DD * DD,
                                       wtl0 + (size_t)DD * DD, DD, DD,
                                       khi, klo, nullptr, nullptr, 0.f);
    mma_gemm<2, 1><<<gQKV, blk, SM2>>>(xhi, xlo, wth0 + (size_t)2 * DD * DD,
                                       wtl0 + (size_t)2 * DD * DD, DD, DD,
                                       vb, nullptr, nullptr, nullptr, 0.f);
    trans_v_k<<<dim3(DD / 32, NR / 32), dim3(32, 8)>>>();

    // E = exp(q k^T / sqrt(d)) (global-max pass dropped; see R1 analysis), rowsum
    mma_gemm<2, 2><<<dim3(NR / 128, NR / 128), blk, SM2>>>(qhi, qlo, khi, klo, NR, DD,
                                                           E, nullptr, nullptr, rs, SC2);
    // out = (E v) / rowsum
    mma_gemm<1, 3><<<dim3(DD / 128, NR / 128), blk, SM1>>>(E, nullptr, vt, nullptr, DD, NR,
                                                           nullptr, nullptr, out, rs, 0.f);
}

// round 4
// speedup vs baseline: 3.4141x; 1.1773x over previous
#include <cuda_runtime.h>
#include <cuda_bf16.h>
#include <stdint.h>
#include <math.h>

#define NR 8192
#define DD 512

// ---------------- scratch (__device__ globals; no allocs allowed) ----------------
__device__ __align__(128) __nv_bfloat16 g_xhi[(size_t)NR * DD];
__device__ __align__(128) __nv_bfloat16 g_xlo[(size_t)NR * DD];
__device__ __align__(128) __nv_bfloat16 g_wth[3][(size_t)DD * DD];   // W^T hi
__device__ __align__(128) __nv_bfloat16 g_wtl[3][(size_t)DD * DD];   // W^T lo
__device__ __align__(128) __nv_bfloat16 g_qhi[(size_t)NR * DD];
__device__ __align__(128) __nv_bfloat16 g_qlo[(size_t)NR * DD];
__device__ __align__(128) __nv_bfloat16 g_khi[(size_t)NR * DD];
__device__ __align__(128) __nv_bfloat16 g_klo[(size_t)NR * DD];
__device__ __align__(128) __nv_bfloat16 g_vb [(size_t)NR * DD];
__device__ __align__(128) __nv_bfloat16 g_vt [(size_t)DD * NR];      // v^T
__device__ __align__(128) __nv_bfloat16 g_E  [(size_t)NR * NR];      // 128 MB
__device__ float g_rowsum[NR];

// ---------------- helpers (arch-generic PTX: ldmatrix + mma.sync + cp.async) ---------
__device__ __forceinline__ uint32_t smem_u32(const void* p) {
    uint32_t a;
    asm("{ .reg .u64 t; cvta.to.shared.u64 t, %1; cvt.u32.u64 %0, t; }" : "=r"(a) : "l"(p));
    return a;
}
__device__ __forceinline__ void ldsm4(uint32_t r[4], uint32_t a) {
    asm volatile("ldmatrix.sync.aligned.m8n8.x4.shared.b16 {%0,%1,%2,%3}, [%4];"
                 : "=r"(r[0]), "=r"(r[1]), "=r"(r[2]), "=r"(r[3]) : "r"(a));
}
__device__ __forceinline__ void mma16816(float d[4], const uint32_t a[4], const uint32_t b[2]) {
    asm volatile("mma.sync.aligned.m16n8k16.row.col.f32.bf16.bf16.f32 "
                 "{%0,%1,%2,%3}, {%4,%5,%6,%7}, {%8,%9}, {%0,%1,%2,%3};"
                 : "+f"(d[0]), "+f"(d[1]), "+f"(d[2]), "+f"(d[3])
                 : "r"(a[0]), "r"(a[1]), "r"(a[2]), "r"(a[3]), "r"(b[0]), "r"(b[1]));
}
__device__ __forceinline__ void cp16(uint32_t saddr, const void* gaddr) {
    asm volatile("cp.async.cg.shared.global [%0], [%1], 16;" :: "r"(saddr), "l"(gaddr));
}
#define CP_COMMIT() asm volatile("cp.async.commit_group;" ::: "memory")
#define CP_WAIT1()  asm volatile("cp.async.wait_group 1;" ::: "memory")

__device__ __forceinline__ float exp2_poly(float t) {
    float fi = rintf(t);
    float f = t - fi;
    float p = 0.00015403530393381606f;
    p = fmaf(p, f, 0.0013333558146428443f);
    p = fmaf(p, f, 0.009618129107628477f);
    p = fmaf(p, f, 0.05550410866482158f);
    p = fmaf(p, f, 0.2402265069591007f);
    p = fmaf(p, f, 0.6931471805599453f);
    p = fmaf(p, f, 1.0f);
    return __int_as_float(((int)fi + 127) << 23) * p;
}

// ---------------- small prep kernels ----------------
__global__ void zero_rowsum_k() { g_rowsum[blockIdx.x * blockDim.x + threadIdx.x] = 0.0f; }

__global__ void split_x_k(const float4* __restrict__ x) {
    size_t i = (size_t)blockIdx.x * 256 + threadIdx.x;
    float4 v = x[i];
    __nv_bfloat16 hx = __float2bfloat16(v.x), hy = __float2bfloat16(v.y);
    __nv_bfloat16 hz = __float2bfloat16(v.z), hw = __float2bfloat16(v.w);
    __nv_bfloat162* H = (__nv_bfloat162*)g_xhi;
    __nv_bfloat162* L = (__nv_bfloat162*)g_xlo;
    H[2 * i]     = __halves2bfloat162(hx, hy);
    H[2 * i + 1] = __halves2bfloat162(hz, hw);
    L[2 * i]     = __halves2bfloat162(__float2bfloat16(v.x - __bfloat162float(hx)),
                                      __float2bfloat16(v.y - __bfloat162float(hy)));
    L[2 * i + 1] = __halves2bfloat162(__float2bfloat16(v.z - __bfloat162float(hz)),
                                      __float2bfloat16(v.w - __bfloat162float(hw)));
}

__global__ void trans_split_w_k(const float* __restrict__ W,
                                __nv_bfloat16* __restrict__ Th,
                                __nv_bfloat16* __restrict__ Tl) {
    __shared__ float t[32][33];
    int tx = threadIdx.x, ty = threadIdx.y;
    int xi = blockIdx.x * 32 + tx, yi = blockIdx.y * 32 + ty;
    #pragma unroll
    for (int i = 0; i < 32; i += 8) t[ty + i][tx] = W[(size_t)(yi + i) * DD + xi];
    __syncthreads();
    int xo = blockIdx.y * 32 + tx, yo = blockIdx.x * 32 + ty;
    #pragma unroll
    for (int i = 0; i < 32; i += 8) {
        float v = t[tx][ty + i];
        __nv_bfloat16 h = __float2bfloat16(v);
        Th[(size_t)(yo + i) * DD + xo] = h;
        Tl[(size_t)(yo + i) * DD + xo] = __float2bfloat16(v - __bfloat162float(h));
    }
}

__global__ void trans_v_k() {
    __shared__ __nv_bfloat16 t[32][33];
    int tx = threadIdx.x, ty = threadIdx.y;
    int xi = blockIdx.x * 32 + tx, yi = blockIdx.y * 32 + ty;
    #pragma unroll
    for (int i = 0; i < 32; i += 8) t[ty + i][tx] = g_vb[(size_t)(yi + i) * DD + xi];
    __syncthreads();
    int xo = blockIdx.y * 32 + tx, yo = blockIdx.x * 32 + ty;
    #pragma unroll
    for (int i = 0; i < 32; i += 8) g_vt[(size_t)(yo + i) * NR + xo] = t[tx][ty + i];
}

// ============ mma.sync GEMM: D[M,Ncols] = A[M,K] x B[Ncols,K]^T, bf16, fp32 accum ========
// NOP=2: acc = Ahi*Bhi + Ahi*Blo + Alo*Bhi   NOP=1: acc = A*B
// EPI 0: abs -> split (Chi, Clo)   EPI 1: abs -> bf16 (Chi)
// EPI 2: exp2(acc*scale) -> bf16 Chi + rowsum atomics   EPI 3: acc/rowsum -> f32 Cf
// Block 128x128, BK=32, 8 warps (2m x 4n), warp 64x32 (4x4 m16n8k16).
// cp.async 3-stage pipeline; smem 64B rows, swizzle: unit' = unit ^ ((row>>1)&3).
template<int NOP, int EPI>
__global__ __launch_bounds__(256, 1)
void mma_gemm(const __nv_bfloat16* __restrict__ Ahi, const __nv_bfloat16* __restrict__ Alo,
              const __nv_bfloat16* __restrict__ Bhi, const __nv_bfloat16* __restrict__ Blo,
              int Ncols, int K,
              __nv_bfloat16* __restrict__ Chi, __nv_bfloat16* __restrict__ Clo,
              float* __restrict__ Cf, float* __restrict__ rsum, float scale)
{
    constexpr int NT = 2 * NOP;                 // tiles per stage
    constexpr int NS = 3;                        // pipeline stages
    constexpr uint32_t STAGE = (uint32_t)NT * 8192u;
    extern __shared__ char dyn[];
    __shared__ float red[128][4];

    const int tid = threadIdx.x;
    const int lane = tid & 31, wid = tid >> 5;
    const int wm = wid & 1, wn = wid >> 1;
    const int m0 = blockIdx.y * 128, n0 = blockIdx.x * 128;
    const uint32_t sbase = smem_u32(dyn);

    const __nv_bfloat16* gsrc[NT];
    int rb[NT];
    if (NOP == 2) {
        gsrc[0] = Ahi; rb[0] = m0;
        gsrc[1] = Alo; rb[1] = m0;
        gsrc[2] = Bhi; rb[2] = n0;
        gsrc[3] = Blo; rb[3] = n0;
    } else {
        gsrc[0] = Ahi; rb[0] = m0;
        gsrc[1] = Bhi; rb[1] = n0;
    }

    // cp.async mapping: thread covers 16B units at rows sr0, sr0+64, unit su, per tile
    const int su = tid & 3;
    const int sr0 = tid >> 2, sr1 = sr0 + 64;
    const uint32_t soff0 = sr0 * 64 + ((su ^ ((sr0 >> 1) & 3)) << 4);
    const uint32_t soff1 = sr1 * 64 + ((su ^ ((sr1 >> 1) & 3)) << 4);

    // ldmatrix per-lane byte offsets (within a tile)
    uint32_t offA[4][2], offB[2][2];
    {
        const int ra = lane & 15, ua = lane >> 4;
        #pragma unroll
        for (int mi = 0; mi < 4; mi++)
            #pragma unroll
            for (int ks = 0; ks < 2; ks++) {
                int r = wm * 64 + mi * 16 + ra;
                int u = ks * 2 + ua;
                offA[mi][ks] = r * 64 + ((u ^ ((r >> 1) & 3)) << 4);
            }
        const int rbv = ((lane >> 4) << 3) + (lane & 7), ub = (lane >> 3) & 1;
        #pragma unroll
        for (int np = 0; np < 2; np++)
            #pragma unroll
            for (int ks = 0; ks < 2; ks++) {
                int r = wn * 32 + np * 16 + rbv;
                int u = ks * 2 + ub;
                offB[np][ks] = r * 64 + ((u ^ ((r >> 1) & 3)) << 4);
            }
    }

    float acc[4][4][4];
    #pragma unroll
    for (int a = 0; a < 4; a++)
        #pragma unroll
        for (int b = 0; b < 4; b++)
            #pragma unroll
            for (int c = 0; c < 4; c++) acc[a][b][c] = 0.0f;

    const int nkt = K >> 5;

    // prologue: stage chunks 0, 1
    #pragma unroll
    for (int s = 0; s < NS - 1; s++) {
        const int kc = s * 32 + su * 8;
        const uint32_t db = sbase + (uint32_t)s * STAGE;
        #pragma unroll
        for (int t = 0; t < NT; t++) {
            cp16(db + t * 8192u + soff0, gsrc[t] + (size_t)(rb[t] + sr0) * K + kc);
            cp16(db + t * 8192u + soff1, gsrc[t] + (size_t)(rb[t] + sr1) * K + kc);
        }
        CP_COMMIT();
    }

    int stage = 0;
    for (int kt = 0; kt < nkt; kt++) {
        // issue chunk kt+2 into the stage buffer freed at end of iteration kt-1
        if (kt + NS - 1 < nkt) {
            const int ldst = (stage + NS - 1) % NS;
            const int kc = (kt + NS - 1) * 32 + su * 8;
            const uint32_t db = sbase + (uint32_t)ldst * STAGE;
            #pragma unroll
            for (int t = 0; t < NT; t++) {
                cp16(db + t * 8192u + soff0, gsrc[t] + (size_t)(rb[t] + sr0) * K + kc);
                cp16(db + t * 8192u + soff1, gsrc[t] + (size_t)(rb[t] + sr1) * K + kc);
            }
        }
        CP_COMMIT();
        CP_WAIT1();          // chunk kt resident
        __syncthreads();

        const uint32_t bb = sbase + (uint32_t)stage * STAGE;
        #pragma unroll
        for (int ks = 0; ks < 2; ks++) {
            uint32_t ah[4][4];
            #pragma unroll
            for (int mi = 0; mi < 4; mi++) ldsm4(ah[mi], bb + offA[mi][ks]);
            uint32_t bh[2][4];
            constexpr uint32_t TBH = (NOP == 2) ? 2u * 8192u : 1u * 8192u;
            #pragma unroll
            for (int np = 0; np < 2; np++) ldsm4(bh[np], bb + TBH + offB[np][ks]);
            #pragma unroll
            for (int mi = 0; mi < 4; mi++)
                #pragma unroll
                for (int ni = 0; ni < 4; ni++)
                    mma16816(acc[mi][ni], ah[mi], &bh[ni >> 1][(ni & 1) * 2]);
            if (NOP == 2) {
                uint32_t bl[2][4];
                #pragma unroll
                for (int np = 0; np < 2; np++) ldsm4(bl[np], bb + 3u * 8192u + offB[np][ks]);
                #pragma unroll
                for (int mi = 0; mi < 4; mi++)
                    #pragma unroll
                    for (int ni = 0; ni < 4; ni++)
                        mma16816(acc[mi][ni], ah[mi], &bl[ni >> 1][(ni & 1) * 2]);
                uint32_t al[4][4];
                #pragma unroll
                for (int mi = 0; mi < 4; mi++) ldsm4(al[mi], bb + 1u * 8192u + offA[mi][ks]);
                #pragma unroll
                for (int mi = 0; mi < 4; mi++)
                    #pragma unroll
                    for (int ni = 0; ni < 4; ni++)
                        mma16816(acc[mi][ni], al[mi], &bh[ni >> 1][(ni & 1) * 2]);
            }
        }
        __syncthreads();     // stage buffer free for reuse by next iteration's issue
        stage = (stage + 1 < NS) ? stage + 1 : 0;
    }

    // -------- epilogue --------
    const int lr = lane >> 2;
    const int lc = (lane & 3) << 1;

    #pragma unroll
    for (int mi = 0; mi < 4; mi++) {
        #pragma unroll
        for (int h = 0; h < 2; h++) {
            const int lrow = wm * 64 + mi * 16 + h * 8 + lr;
            const int grow = m0 + lrow;
            float part = 0.0f;
            float invr = 0.0f;
            if (EPI == 3) invr = 1.0f / rsum[grow];
            #pragma unroll
            for (int ni = 0; ni < 4; ni++) {
                float v0 = acc[mi][ni][h * 2 + 0];
                float v1 = acc[mi][ni][h * 2 + 1];
                const int gcol = n0 + wn * 32 + ni * 8 + lc;
                const size_t o = (size_t)grow * Ncols + gcol;
                if (EPI == 0) {
                    float y0 = fabsf(v0), y1 = fabsf(v1);
                    __nv_bfloat16 h0 = __float2bfloat16(y0), h1 = __float2bfloat16(y1);
                    __nv_bfloat16 l0 = __float2bfloat16(y0 - __bfloat162float(h0));
                    __nv_bfloat16 l1 = __float2bfloat16(y1 - __bfloat162float(h1));
                    *(__nv_bfloat162*)(Chi + o) = __halves2bfloat162(h0, h1);
                    *(__nv_bfloat162*)(Clo + o) = __halves2bfloat162(l0, l1);
                } else if (EPI == 1) {
                    *(__nv_bfloat162*)(Chi + o) =
                        __halves2bfloat162(__float2bfloat16(fabsf(v0)),
                                           __float2bfloat16(fabsf(v1)));
                } else if (EPI == 2) {
                    float e0 = exp2_poly(v0 * scale);
                    float e1 = exp2_poly(v1 * scale);
                    part += e0 + e1;
                    *(__nv_bfloat162*)(Chi + o) =
                        __halves2bfloat162(__float2bfloat16(e0), __float2bfloat16(e1));
                } else {
                    *(float2*)(Cf + o) = make_float2(v0 * invr, v1 * invr);
                }
            }
            if (EPI == 2) {
                part += __shfl_xor_sync(0xffffffffu, part, 1);
                part += __shfl_xor_sync(0xffffffffu, part, 2);
                if ((lane & 3) == 0) red[lrow][wn] = part;
            }
        }
    }
    if (EPI == 2) {
        __syncthreads();
        if (tid < 128)
            atomicAdd(&rsum[m0 + tid],
                      red[tid][0] + red[tid][1] + red[tid][2] + red[tid][3]);
    }
}

// ---------------- launch ----------------
extern "C" void kernel_launch(void* const* d_in, const int* in_sizes, int n_in,
                              void* d_out, int out_size)
{
    (void)in_sizes; (void)n_in; (void)out_size;
    const float* x  = (const float*)d_in[0];
    const float* W[3] = {(const float*)d_in[1], (const float*)d_in[2], (const float*)d_in[3]};
    float* out = (float*)d_out;

    __nv_bfloat16 *xhi, *xlo, *wth0, *wtl0, *qhi, *qlo, *khi, *klo, *vb, *vt, *E;
    float* rs;
    cudaGetSymbolAddress((void**)&xhi, g_xhi);
    cudaGetSymbolAddress((void**)&xlo, g_xlo);
    cudaGetSymbolAddress((void**)&wth0, g_wth);
    cudaGetSymbolAddress((void**)&wtl0, g_wtl);
    cudaGetSymbolAddress((void**)&qhi, g_qhi);
    cudaGetSymbolAddress((void**)&qlo, g_qlo);
    cudaGetSymbolAddress((void**)&khi, g_khi);
    cudaGetSymbolAddress((void**)&klo, g_klo);
    cudaGetSymbolAddress((void**)&vb,  g_vb);
    cudaGetSymbolAddress((void**)&vt,  g_vt);
    cudaGetSymbolAddress((void**)&E,   g_E);
    cudaGetSymbolAddress((void**)&rs,  g_rowsum);

    const int SM2 = 3 * 4 * 8192 * 2 / 2;   // 3 stages x 4 tiles x 8KB = 96KB
    const int SM1 = 3 * 2 * 8192;           // 3 stages x 2 tiles x 8KB = 48KB
    cudaFuncSetAttribute(mma_gemm<2, 0>, cudaFuncAttributeMaxDynamicSharedMemorySize, SM2);
    cudaFuncSetAttribute(mma_gemm<2, 1>, cudaFuncAttributeMaxDynamicSharedMemorySize, SM2);
    cudaFuncSetAttribute(mma_gemm<2, 2>, cudaFuncAttributeMaxDynamicSharedMemorySize, SM2);
    cudaFuncSetAttribute(mma_gemm<1, 3>, cudaFuncAttributeMaxDynamicSharedMemorySize, SM1);

    const float SC2 = 0.06375869843f;       // log2(e)/sqrt(512)

    split_x_k<<<(NR * DD / 4) / 256, 256>>>((const float4*)x);
    for (int i = 0; i < 3; i++)
        trans_split_w_k<<<dim3(16, 16), dim3(32, 8)>>>(W[i], wth0 + (size_t)i * DD * DD,
                                                       wtl0 + (size_t)i * DD * DD);
    zero_rowsum_k<<<NR / 256, 256>>>();

    dim3 blk(256);
    dim3 gQKV(DD / 128, NR / 128);

    mma_gemm<2, 0><<<gQKV, blk, SM2>>>(xhi, xlo, wth0, wtl0, DD, DD,
                                       qhi, qlo, nullptr, nullptr, 0.f);
    mma_gemm<2, 0><<<gQKV, blk, SM2>>>(xhi, xlo, wth0 + (size_t)DD * DD,
                                       wtl0 + (size_t)DD * DD, DD, DD,
                                       khi, klo, nullptr, nullptr, 0.f);
    mma_gemm<2, 1><<<gQKV, blk, SM2>>>(xhi, xlo, wth0 + (size_t)2 * DD * DD,
                                       wtl0 + (size_t)2 * DD * DD, DD, DD,
                                       vb, nullptr, nullptr, nullptr, 0.f);
    trans_v_k<<<dim3(DD / 32, NR / 32), dim3(32, 8)>>>();

    // E = exp(q k^T / sqrt(d)) (global-max pass dropped; see R1 analysis), rowsum
    mma_gemm<2, 2><<<dim3(NR / 128, NR / 128), blk, SM2>>>(qhi, qlo, khi, klo, NR, DD,
                                                           E, nullptr, nullptr, rs, SC2);
    // out = (E v) / rowsum
    mma_gemm<1, 3><<<dim3(DD / 128, NR / 128), blk, SM1>>>(E, nullptr, vt, nullptr, DD, NR,
                                                           nullptr, nullptr, out, rs, 0.f);
}